// round 12
// baseline (speedup 1.0000x reference)
#include <cuda_runtime.h>
#include <cuda_fp16.h>
#include <math.h>
#include <stdint.h>

#define BATCH 16384
#define IN_CH 4096
#define COMP  512

// ---------------- scratch (__device__ globals; no allocation allowed) ----------------
__device__ __half g_x [(size_t)BATCH * IN_CH];   // fp16 x
__device__ __half g_h [(size_t)BATCH * IN_CH];   // fp16 activations (reused)
__device__ __half g_z [(size_t)BATCH * COMP];
__device__ __half g_wt1[(size_t)IN_CH * IN_CH];  // enc_w1^T  [N,K] fp16
__device__ __half g_wt2[(size_t)COMP  * IN_CH];
__device__ __half g_wt3[(size_t)IN_CH * COMP];
__device__ __half g_wt4[(size_t)IN_CH * IN_CH];

// ---------------- helpers ----------------
__device__ __forceinline__ uint32_t smem_u32(const void* p) {
    uint32_t a;
    asm("{ .reg .u64 t; cvta.to.shared.u64 t, %1; cvt.u32.u64 %0, t; }" : "=r"(a) : "l"(p));
    return a;
}

#define CP_ASYNC16(saddr, gaddr) \
    asm volatile("cp.async.cg.shared.global [%0], [%1], 16;" :: "r"(saddr), "l"(gaddr) : "memory")
#define CP_COMMIT() asm volatile("cp.async.commit_group;" ::: "memory")
#define CP_WAIT(n)  asm volatile("cp.async.wait_group %0;" :: "n"(n) : "memory")

__device__ __forceinline__ void ldsm4(uint32_t* r, uint32_t addr) {
    asm volatile("ldmatrix.sync.aligned.m8n8.x4.shared.b16 {%0,%1,%2,%3}, [%4];"
                 : "=r"(r[0]), "=r"(r[1]), "=r"(r[2]), "=r"(r[3]) : "r"(addr));
}

__device__ __forceinline__ void mma_f16(float* d, uint32_t a0, uint32_t a1, uint32_t a2, uint32_t a3,
                                        uint32_t b0, uint32_t b1) {
    asm volatile("mma.sync.aligned.m16n8k16.row.col.f32.f16.f16.f32 "
                 "{%0,%1,%2,%3}, {%4,%5,%6,%7}, {%8,%9}, {%0,%1,%2,%3};"
                 : "+f"(d[0]), "+f"(d[1]), "+f"(d[2]), "+f"(d[3])
                 : "r"(a0), "r"(a1), "r"(a2), "r"(a3), "r"(b0), "r"(b1));
}

// ---------------- JAX Threefry noise (verified bit-exact in round 0) ----------------
__device__ __forceinline__ unsigned rotl32(unsigned v, int r) { return (v << r) | (v >> (32 - r)); }
__device__ __forceinline__ unsigned threefry2x32_xor(unsigned c_hi, unsigned c_lo) {
    const unsigned k1 = 0u, k2 = 42u, k3 = 0x1BD11BDAu ^ k1 ^ k2;
    unsigned x0 = c_hi + k1, x1 = c_lo + k2;
#define TFR(r) { x0 += x1; x1 = rotl32(x1, (r)); x1 ^= x0; }
    TFR(13) TFR(15) TFR(26) TFR(6)
    x0 += k2; x1 += k3 + 1u;
    TFR(17) TFR(29) TFR(16) TFR(24)
    x0 += k3; x1 += k1 + 2u;
    TFR(13) TFR(15) TFR(26) TFR(6)
    x0 += k1; x1 += k2 + 3u;
    TFR(17) TFR(29) TFR(16) TFR(24)
    x0 += k2; x1 += k3 + 4u;
    TFR(13) TFR(15) TFR(26) TFR(6)
    x0 += k3; x1 += k1 + 5u;
#undef TFR
    return x0 ^ x1;
}
__device__ __forceinline__ float jax_awgn_noise(unsigned idx) {
    unsigned bits = threefry2x32_xor(0u, idx);
    float f = __uint_as_float((bits >> 9) | 0x3F800000u) - 1.0f;
    const float lo = -0.99999994f;
    float u = fmaxf(lo, fmaf(f, 2.0f, lo));
    return 1.41421356f * erfinvf(u) * 0.223341852f;
}

// ---------------- prep kernels ----------------
__global__ void f32_to_f16_kernel(const float4* __restrict__ in, __half2* __restrict__ out, int n4) {
    for (int i = blockIdx.x * blockDim.x + threadIdx.x; i < n4; i += gridDim.x * blockDim.x) {
        float4 v = in[i];
        out[i * 2]     = __floats2half2_rn(v.x, v.y);
        out[i * 2 + 1] = __floats2half2_rn(v.z, v.w);
    }
}
// out[c][r] = f16(in[r][c]); in is [R, C] f32
__global__ void transpose_f16_kernel(const float* __restrict__ in, __half* __restrict__ out, int R, int C) {
    __shared__ float t[32][33];
    int c0 = blockIdx.x * 32, r0 = blockIdx.y * 32;
    int x = threadIdx.x, y = threadIdx.y;
    for (int i = y; i < 32; i += 8) t[i][x] = in[(size_t)(r0 + i) * C + c0 + x];
    __syncthreads();
    for (int i = y; i < 32; i += 8) out[(size_t)(c0 + i) * R + r0 + x] = __float2half_rn(t[x][i]);
}

// ---------------- fp16 mma.sync GEMM (ldmatrix b16, BK=64, frag ping-pong) ----------------
// C[M,N] = ep(A[M,K] @ B^T + bias), A,B fp16, B stored [N,K]. CTA tile 128x128x64.
// 8 warps as 4(M) x 2(N): warp tile 32x64 = 2 x 8 m16n8k16 tiles per k16-step (4 steps/chunk).

#define BM 128
#define BN 128
#define BK 64
#define NSTAGE 3
#define LDT 72                            // halves; 144B row stride -> conflict-free LDSM+STS
#define TILE_H (128 * LDT)                // 9216 halves per operand tile
#define STAGE_H (2 * TILE_H)              // 18432 halves
#define SMEM_BYTES (NSTAGE * STAGE_H * 2) // 110592

enum { EP_RELU = 0, EP_CLAMP_NOISE = 1, EP_PLAIN = 2 };

// load a 128x64 fp16 tile (row stride ldg halves) into padded smem tile (256 threads).
// STS banks (36r+4q) mod 32 — conflict-free; 8 lanes read 128B contiguous (coalesced).
__device__ __forceinline__ void load_tile16(__half* sdst, const __half* gsrc, int ldg, int tid) {
#pragma unroll
    for (int i = 0; i < 4; i++) {
        int idx = tid + i * 256;           // 0..1023
        int row = idx >> 3;
        int q   = idx & 7;                 // 16B (8 halves) chunk within 64-half row
        uint32_t sa = smem_u32(sdst + row * LDT + q * 8);
        const __half* ga = gsrc + (size_t)row * ldg + q * 8;
        CP_ASYNC16(sa, ga);
    }
}

template <int MODE, typename OutT>
__global__ __launch_bounds__(256, 2)
void gemm_mma(const __half* __restrict__ A, const __half* __restrict__ B,
              const float* __restrict__ bias, OutT* __restrict__ C,
              int M, int N, int K)
{
    extern __shared__ __half sm[];
    const int tid = threadIdx.x;
    const int wid = tid >> 5;
    const int lane = tid & 31;
    const int g = lane >> 2;              // fragment row
    const int tig = lane & 3;
    const int qt = lane >> 3;             // ldmatrix tile id 0..3
    const int rr = lane & 7;              // row within ldmatrix tile

    const int n0 = blockIdx.x * BN;
    const int m0 = blockIdx.y * BM;
    const int warp_m = (wid >> 1) * 32;   // 0,32,64,96
    const int warp_n = (wid & 1) * 64;    // 0,64
    const int nchunk = K >> 6;            // BK=64

    const __half* Ab = A + (size_t)m0 * K;
    const __half* Bb = B + (size_t)n0 * K;

    const uint32_t smb = smem_u32(sm);
    // per-lane ldmatrix byte offsets (k=0) within a stage
    uint32_t a_loff[2], b_loff[4];
#pragma unroll
    for (int mt = 0; mt < 2; mt++)
        a_loff[mt] = ((warp_m + mt * 16 + ((qt & 1) << 3) + rr) * LDT + ((qt >> 1) << 3)) * 2;
#pragma unroll
    for (int p = 0; p < 4; p++)
        b_loff[p] = (TILE_H + (warp_n + p * 16 + ((qt >> 1) << 3) + rr) * LDT + ((qt & 1) << 3)) * 2;

    float acc[2][8][4];
#pragma unroll
    for (int mt = 0; mt < 2; mt++)
#pragma unroll
        for (int nt = 0; nt < 8; nt++)
#pragma unroll
            for (int q = 0; q < 4; q++) acc[mt][nt][q] = 0.0f;

    // prologue: issue stages 0..NSTAGE-2
#pragma unroll
    for (int s = 0; s < NSTAGE - 1; s++) {
        __half* st = sm + s * STAGE_H;
        load_tile16(st, Ab + s * BK, K, tid);
        load_tile16(st + TILE_H, Bb + s * BK, K, tid);
        CP_COMMIT();
    }

    for (int c = 0; c < nchunk; c++) {
        CP_WAIT(NSTAGE - 2);
        __syncthreads();

        if (c + NSTAGE - 1 < nchunk) {
            int s = (c + NSTAGE - 1) % NSTAGE;
            __half* st = sm + s * STAGE_H;
            load_tile16(st, Ab + (c + NSTAGE - 1) * BK, K, tid);
            load_tile16(st + TILE_H, Bb + (c + NSTAGE - 1) * BK, K, tid);
            CP_COMMIT();
        }

        const uint32_t stg = smb + (uint32_t)((c % NSTAGE) * STAGE_H * 2);

        // ---- fragment ping-pong across the 4 k16-steps ----
        uint32_t af[2][2][4], bf[2][4][4];
        ldsm4(af[0][0], stg + a_loff[0]);
        ldsm4(af[0][1], stg + a_loff[1]);
#pragma unroll
        for (int p = 0; p < 4; p++) ldsm4(bf[0][p], stg + b_loff[p]);

#pragma unroll
        for (int ks = 0; ks < 4; ks++) {
            const int cur = ks & 1;
            const int nxt = cur ^ 1;
            if (ks < 3) {                              // prefetch ks+1 fragments
                const uint32_t kb = (ks + 1) * 32;
                ldsm4(af[nxt][0], stg + a_loff[0] + kb);
                ldsm4(af[nxt][1], stg + a_loff[1] + kb);
#pragma unroll
                for (int p = 0; p < 4; p++) ldsm4(bf[nxt][p], stg + b_loff[p] + kb);
            }
#pragma unroll
            for (int mt = 0; mt < 2; mt++)
#pragma unroll
                for (int nt = 0; nt < 8; nt++)
                    mma_f16(acc[mt][nt], af[cur][mt][0], af[cur][mt][1], af[cur][mt][2], af[cur][mt][3],
                            bf[cur][nt >> 1][(nt & 1) * 2], bf[cur][nt >> 1][(nt & 1) * 2 + 1]);
        }
    }
    CP_WAIT(0);

    // ---- epilogue ----
#pragma unroll
    for (int mt = 0; mt < 2; mt++) {
        const int row_a = m0 + warp_m + mt * 16 + g;
        const int row_b = row_a + 8;
#pragma unroll
        for (int nt = 0; nt < 8; nt++) {
            const int col = n0 + warp_n + nt * 8 + tig * 2;
            const float b0 = bias[col], b1 = bias[col + 1];
            float v0 = acc[mt][nt][0] + b0;
            float v1 = acc[mt][nt][1] + b1;
            float v2 = acc[mt][nt][2] + b0;
            float v3 = acc[mt][nt][3] + b1;
            if (MODE == EP_RELU) {
                v0 = fmaxf(v0, 0.0f); v1 = fmaxf(v1, 0.0f);
                v2 = fmaxf(v2, 0.0f); v3 = fmaxf(v3, 0.0f);
            } else if (MODE == EP_CLAMP_NOISE) {
                v0 = fminf(fmaxf(v0, 0.0f), 1.0f) + jax_awgn_noise((unsigned)((size_t)row_a * N + col));
                v1 = fminf(fmaxf(v1, 0.0f), 1.0f) + jax_awgn_noise((unsigned)((size_t)row_a * N + col + 1));
                v2 = fminf(fmaxf(v2, 0.0f), 1.0f) + jax_awgn_noise((unsigned)((size_t)row_b * N + col));
                v3 = fminf(fmaxf(v3, 0.0f), 1.0f) + jax_awgn_noise((unsigned)((size_t)row_b * N + col + 1));
            }
            if (sizeof(OutT) == 2) {
                __half* Ch = (__half*)C;
                *(__half2*)(Ch + (size_t)row_a * N + col) = __floats2half2_rn(v0, v1);
                *(__half2*)(Ch + (size_t)row_b * N + col) = __floats2half2_rn(v2, v3);
            } else {
                float* Cf = (float*)C;
                *(float2*)(Cf + (size_t)row_a * N + col) = make_float2(v0, v1);
                *(float2*)(Cf + (size_t)row_b * N + col) = make_float2(v2, v3);
            }
        }
    }
}

// ---------------- host launch ----------------
extern "C" void kernel_launch(void* const* d_in, const int* in_sizes, int n_in,
                              void* d_out, int out_size)
{
    (void)in_sizes; (void)n_in; (void)out_size;
    const float* x   = (const float*)d_in[0];
    const float* ew1 = (const float*)d_in[1];
    const float* eb1 = (const float*)d_in[2];
    const float* ew2 = (const float*)d_in[3];
    const float* eb2 = (const float*)d_in[4];
    const float* dw1 = (const float*)d_in[5];
    const float* db1 = (const float*)d_in[6];
    const float* dw2 = (const float*)d_in[7];
    const float* db2 = (const float*)d_in[8];
    float* out = (float*)d_out;

    __half *px, *ph, *pz, *w1, *w2, *w3, *w4;
    cudaGetSymbolAddress((void**)&px, g_x);
    cudaGetSymbolAddress((void**)&ph, g_h);
    cudaGetSymbolAddress((void**)&pz, g_z);
    cudaGetSymbolAddress((void**)&w1, g_wt1);
    cudaGetSymbolAddress((void**)&w2, g_wt2);
    cudaGetSymbolAddress((void**)&w3, g_wt3);
    cudaGetSymbolAddress((void**)&w4, g_wt4);

    // prep: x -> fp16; transpose weights -> [N,K] fp16
    f32_to_f16_kernel<<<2048, 256>>>((const float4*)x, (__half2*)px, (BATCH * IN_CH) / 4);
    dim3 tb(32, 8);
    transpose_f16_kernel<<<dim3(IN_CH / 32, IN_CH / 32), tb>>>(ew1, w1, IN_CH, IN_CH);
    transpose_f16_kernel<<<dim3(COMP  / 32, IN_CH / 32), tb>>>(ew2, w2, IN_CH, COMP);
    transpose_f16_kernel<<<dim3(IN_CH / 32, COMP  / 32), tb>>>(dw1, w3, COMP, IN_CH);
    transpose_f16_kernel<<<dim3(IN_CH / 32, IN_CH / 32), tb>>>(dw2, w4, IN_CH, IN_CH);

    cudaFuncSetAttribute((void*)gemm_mma<EP_RELU, __half>,        cudaFuncAttributeMaxDynamicSharedMemorySize, SMEM_BYTES);
    cudaFuncSetAttribute((void*)gemm_mma<EP_CLAMP_NOISE, __half>, cudaFuncAttributeMaxDynamicSharedMemorySize, SMEM_BYTES);
    cudaFuncSetAttribute((void*)gemm_mma<EP_PLAIN, float>,        cudaFuncAttributeMaxDynamicSharedMemorySize, SMEM_BYTES);

    // G1: h = relu(x @ enc_w1 + b)            [16384, 4096], K=4096
    gemm_mma<EP_RELU, __half><<<dim3(IN_CH / BN, BATCH / BM), 256, SMEM_BYTES>>>(px, w1, eb1, ph, BATCH, IN_CH, IN_CH);
    // G2: z = clamp(h @ enc_w2 + b) + awgn    [16384, 512],  K=4096
    gemm_mma<EP_CLAMP_NOISE, __half><<<dim3(COMP / BN, BATCH / BM), 256, SMEM_BYTES>>>(ph, w2, eb2, pz, BATCH, COMP, IN_CH);
    // G3: h = relu(z @ dec_w1 + b)            [16384, 4096], K=512
    gemm_mma<EP_RELU, __half><<<dim3(IN_CH / BN, BATCH / BM), 256, SMEM_BYTES>>>(pz, w3, db1, ph, BATCH, IN_CH, COMP);
    // G4: out = h @ dec_w2 + b                [16384, 4096], K=4096
    gemm_mma<EP_PLAIN, float><<<dim3(IN_CH / BN, BATCH / BM), 256, SMEM_BYTES>>>(ph, w4, db2, out, BATCH, IN_CH, IN_CH);
}

// round 13
// speedup vs baseline: 1.0590x; 1.0590x over previous
#include <cuda_runtime.h>
#include <cuda_fp16.h>
#include <math.h>
#include <stdint.h>

#define BATCH 16384
#define IN_CH 4096
#define COMP  512

// ---------------- scratch (__device__ globals; no allocation allowed) ----------------
__device__ __half g_x [(size_t)BATCH * IN_CH];   // fp16 x
__device__ __half g_h [(size_t)BATCH * IN_CH];   // fp16 activations (reused)
__device__ __half g_z [(size_t)BATCH * COMP];
__device__ __half g_wt1[(size_t)IN_CH * IN_CH];  // enc_w1^T  [N,K] fp16
__device__ __half g_wt2[(size_t)COMP  * IN_CH];
__device__ __half g_wt3[(size_t)IN_CH * COMP];
__device__ __half g_wt4[(size_t)IN_CH * IN_CH];

// ---------------- helpers ----------------
__device__ __forceinline__ uint32_t smem_u32(const void* p) {
    uint32_t a;
    asm("{ .reg .u64 t; cvta.to.shared.u64 t, %1; cvt.u32.u64 %0, t; }" : "=r"(a) : "l"(p));
    return a;
}

#define CP_ASYNC16(saddr, gaddr) \
    asm volatile("cp.async.cg.shared.global [%0], [%1], 16;" :: "r"(saddr), "l"(gaddr) : "memory")
#define CP_COMMIT() asm volatile("cp.async.commit_group;" ::: "memory")
#define CP_WAIT(n)  asm volatile("cp.async.wait_group %0;" :: "n"(n) : "memory")

__device__ __forceinline__ void ldsm4(uint32_t* r, uint32_t addr) {
    asm volatile("ldmatrix.sync.aligned.m8n8.x4.shared.b16 {%0,%1,%2,%3}, [%4];"
                 : "=r"(r[0]), "=r"(r[1]), "=r"(r[2]), "=r"(r[3]) : "r"(addr));
}

__device__ __forceinline__ void mma_f16(float* d, uint32_t a0, uint32_t a1, uint32_t a2, uint32_t a3,
                                        uint32_t b0, uint32_t b1) {
    asm volatile("mma.sync.aligned.m16n8k16.row.col.f32.f16.f16.f32 "
                 "{%0,%1,%2,%3}, {%4,%5,%6,%7}, {%8,%9}, {%0,%1,%2,%3};"
                 : "+f"(d[0]), "+f"(d[1]), "+f"(d[2]), "+f"(d[3])
                 : "r"(a0), "r"(a1), "r"(a2), "r"(a3), "r"(b0), "r"(b1));
}

// ---------------- JAX Threefry noise (verified bit-exact in round 0) ----------------
__device__ __forceinline__ unsigned rotl32(unsigned v, int r) { return (v << r) | (v >> (32 - r)); }
__device__ __forceinline__ unsigned threefry2x32_xor(unsigned c_hi, unsigned c_lo) {
    const unsigned k1 = 0u, k2 = 42u, k3 = 0x1BD11BDAu ^ k1 ^ k2;
    unsigned x0 = c_hi + k1, x1 = c_lo + k2;
#define TFR(r) { x0 += x1; x1 = rotl32(x1, (r)); x1 ^= x0; }
    TFR(13) TFR(15) TFR(26) TFR(6)
    x0 += k2; x1 += k3 + 1u;
    TFR(17) TFR(29) TFR(16) TFR(24)
    x0 += k3; x1 += k1 + 2u;
    TFR(13) TFR(15) TFR(26) TFR(6)
    x0 += k1; x1 += k2 + 3u;
    TFR(17) TFR(29) TFR(16) TFR(24)
    x0 += k2; x1 += k3 + 4u;
    TFR(13) TFR(15) TFR(26) TFR(6)
    x0 += k3; x1 += k1 + 5u;
#undef TFR
    return x0 ^ x1;
}
__device__ __forceinline__ float jax_awgn_noise(unsigned idx) {
    unsigned bits = threefry2x32_xor(0u, idx);
    float f = __uint_as_float((bits >> 9) | 0x3F800000u) - 1.0f;
    const float lo = -0.99999994f;
    float u = fmaxf(lo, fmaf(f, 2.0f, lo));
    return 1.41421356f * erfinvf(u) * 0.223341852f;
}

// ---------------- prep kernels ----------------
__global__ void f32_to_f16_kernel(const float4* __restrict__ in, __half2* __restrict__ out, int n4) {
    for (int i = blockIdx.x * blockDim.x + threadIdx.x; i < n4; i += gridDim.x * blockDim.x) {
        float4 v = in[i];
        out[i * 2]     = __floats2half2_rn(v.x, v.y);
        out[i * 2 + 1] = __floats2half2_rn(v.z, v.w);
    }
}
// out[c][r] = f16(in[r][c]); in is [R, C] f32
__global__ void transpose_f16_kernel(const float* __restrict__ in, __half* __restrict__ out, int R, int C) {
    __shared__ float t[32][33];
    int c0 = blockIdx.x * 32, r0 = blockIdx.y * 32;
    int x = threadIdx.x, y = threadIdx.y;
    for (int i = y; i < 32; i += 8) t[i][x] = in[(size_t)(r0 + i) * C + c0 + x];
    __syncthreads();
    for (int i = y; i < 32; i += 8) out[(size_t)(c0 + i) * R + r0 + x] = __float2half_rn(t[x][i]);
}

// ---------------- fp16 mma.sync GEMM (ldmatrix b16, BK=64) ----------------
// C[M,N] = ep(A[M,K] @ B^T + bias), A,B fp16, B stored [N,K]. CTA tile 128x128x64.
// 8 warps as 4(M) x 2(N): warp tile 32x64 = 2 x 8 m16n8k16 tiles per k16-step (4 steps/chunk).

#define BM 128
#define BN 128
#define BK 64
#define NSTAGE 3
#define LDT 72                            // halves; 144B row stride -> conflict-free LDSM+STS
#define TILE_H (128 * LDT)                // 9216 halves per operand tile
#define STAGE_H (2 * TILE_H)              // 18432 halves
#define SMEM_BYTES (NSTAGE * STAGE_H * 2) // 110592

enum { EP_RELU = 0, EP_CLAMP_NOISE = 1, EP_PLAIN = 2 };

// load a 128x64 fp16 tile (row stride ldg halves) into padded smem tile (256 threads).
// STS banks (36r+4q) mod 32 — conflict-free; 8 lanes read 128B contiguous (coalesced).
__device__ __forceinline__ void load_tile16(__half* sdst, const __half* gsrc, int ldg, int tid) {
#pragma unroll
    for (int i = 0; i < 4; i++) {
        int idx = tid + i * 256;           // 0..1023
        int row = idx >> 3;
        int q   = idx & 7;                 // 16B (8 halves) chunk within 64-half row
        uint32_t sa = smem_u32(sdst + row * LDT + q * 8);
        const __half* ga = gsrc + (size_t)row * ldg + q * 8;
        CP_ASYNC16(sa, ga);
    }
}

template <int MODE, typename OutT>
__global__ __launch_bounds__(256, 2)
void gemm_mma(const __half* __restrict__ A, const __half* __restrict__ B,
              const float* __restrict__ bias, OutT* __restrict__ C,
              int M, int N, int K)
{
    extern __shared__ __half sm[];
    const int tid = threadIdx.x;
    const int wid = tid >> 5;
    const int lane = tid & 31;
    const int g = lane >> 2;              // fragment row
    const int tig = lane & 3;
    const int qt = lane >> 3;             // ldmatrix tile id 0..3
    const int rr = lane & 7;              // row within ldmatrix tile

    const int n0 = blockIdx.x * BN;
    const int m0 = blockIdx.y * BM;
    const int warp_m = (wid >> 1) * 32;   // 0,32,64,96
    const int warp_n = (wid & 1) * 64;    // 0,64
    const int nchunk = K >> 6;            // BK=64

    const __half* Ab = A + (size_t)m0 * K;
    const __half* Bb = B + (size_t)n0 * K;

    const uint32_t smb = smem_u32(sm);
    // per-lane ldmatrix byte offsets (k=0) within a stage
    uint32_t a_loff[2], b_loff[4];
#pragma unroll
    for (int mt = 0; mt < 2; mt++)
        a_loff[mt] = ((warp_m + mt * 16 + ((qt & 1) << 3) + rr) * LDT + ((qt >> 1) << 3)) * 2;
#pragma unroll
    for (int p = 0; p < 4; p++)
        b_loff[p] = (TILE_H + (warp_n + p * 16 + ((qt >> 1) << 3) + rr) * LDT + ((qt & 1) << 3)) * 2;

    float acc[2][8][4];
#pragma unroll
    for (int mt = 0; mt < 2; mt++)
#pragma unroll
        for (int nt = 0; nt < 8; nt++)
#pragma unroll
            for (int q = 0; q < 4; q++) acc[mt][nt][q] = 0.0f;

    // prologue: issue stages 0..NSTAGE-2
#pragma unroll
    for (int s = 0; s < NSTAGE - 1; s++) {
        __half* st = sm + s * STAGE_H;
        load_tile16(st, Ab + s * BK, K, tid);
        load_tile16(st + TILE_H, Bb + s * BK, K, tid);
        CP_COMMIT();
    }

    for (int c = 0; c < nchunk; c++) {
        CP_WAIT(NSTAGE - 2);
        __syncthreads();

        if (c + NSTAGE - 1 < nchunk) {
            int s = (c + NSTAGE - 1) % NSTAGE;
            __half* st = sm + s * STAGE_H;
            load_tile16(st, Ab + (c + NSTAGE - 1) * BK, K, tid);
            load_tile16(st + TILE_H, Bb + (c + NSTAGE - 1) * BK, K, tid);
            CP_COMMIT();
        }

        const uint32_t stg = smb + (uint32_t)((c % NSTAGE) * STAGE_H * 2);

#pragma unroll
        for (int ks = 0; ks < 4; ks++) {              // four k16 steps per chunk
            const uint32_t kb = ks * 32;              // 16 halves = 32 bytes
            uint32_t af[2][4], bf[4][4];
            // first wave of loads: A frags + B frags for nt 0..3
            ldsm4(af[0], stg + a_loff[0] + kb);
            ldsm4(af[1], stg + a_loff[1] + kb);
            ldsm4(bf[0], stg + b_loff[0] + kb);
            ldsm4(bf[1], stg + b_loff[1] + kb);
            // MMAs for nt 0..3 (need only bf[0], bf[1])
#pragma unroll
            for (int mt = 0; mt < 2; mt++)
#pragma unroll
                for (int nt = 0; nt < 4; nt++)
                    mma_f16(acc[mt][nt], af[mt][0], af[mt][1], af[mt][2], af[mt][3],
                            bf[nt >> 1][(nt & 1) * 2], bf[nt >> 1][(nt & 1) * 2 + 1]);
            // second wave of loads overlapping the MMAs above
            ldsm4(bf[2], stg + b_loff[2] + kb);
            ldsm4(bf[3], stg + b_loff[3] + kb);
            // MMAs for nt 4..7
#pragma unroll
            for (int mt = 0; mt < 2; mt++)
#pragma unroll
                for (int nt = 4; nt < 8; nt++)
                    mma_f16(acc[mt][nt], af[mt][0], af[mt][1], af[mt][2], af[mt][3],
                            bf[nt >> 1][(nt & 1) * 2], bf[nt >> 1][(nt & 1) * 2 + 1]);
        }
    }
    CP_WAIT(0);

    // ---- epilogue ----
#pragma unroll
    for (int mt = 0; mt < 2; mt++) {
        const int row_a = m0 + warp_m + mt * 16 + g;
        const int row_b = row_a + 8;
#pragma unroll
        for (int nt = 0; nt < 8; nt++) {
            const int col = n0 + warp_n + nt * 8 + tig * 2;
            const float b0 = bias[col], b1 = bias[col + 1];
            float v0 = acc[mt][nt][0] + b0;
            float v1 = acc[mt][nt][1] + b1;
            float v2 = acc[mt][nt][2] + b0;
            float v3 = acc[mt][nt][3] + b1;
            if (MODE == EP_RELU) {
                v0 = fmaxf(v0, 0.0f); v1 = fmaxf(v1, 0.0f);
                v2 = fmaxf(v2, 0.0f); v3 = fmaxf(v3, 0.0f);
            } else if (MODE == EP_CLAMP_NOISE) {
                v0 = fminf(fmaxf(v0, 0.0f), 1.0f) + jax_awgn_noise((unsigned)((size_t)row_a * N + col));
                v1 = fminf(fmaxf(v1, 0.0f), 1.0f) + jax_awgn_noise((unsigned)((size_t)row_a * N + col + 1));
                v2 = fminf(fmaxf(v2, 0.0f), 1.0f) + jax_awgn_noise((unsigned)((size_t)row_b * N + col));
                v3 = fminf(fmaxf(v3, 0.0f), 1.0f) + jax_awgn_noise((unsigned)((size_t)row_b * N + col + 1));
            }
            if (sizeof(OutT) == 2) {
                __half* Ch = (__half*)C;
                *(__half2*)(Ch + (size_t)row_a * N + col) = __floats2half2_rn(v0, v1);
                *(__half2*)(Ch + (size_t)row_b * N + col) = __floats2half2_rn(v2, v3);
            } else {
                float* Cf = (float*)C;
                *(float2*)(Cf + (size_t)row_a * N + col) = make_float2(v0, v1);
                *(float2*)(Cf + (size_t)row_b * N + col) = make_float2(v2, v3);
            }
        }
    }
}

// ---------------- host launch ----------------
extern "C" void kernel_launch(void* const* d_in, const int* in_sizes, int n_in,
                              void* d_out, int out_size)
{
    (void)in_sizes; (void)n_in; (void)out_size;
    const float* x   = (const float*)d_in[0];
    const float* ew1 = (const float*)d_in[1];
    const float* eb1 = (const float*)d_in[2];
    const float* ew2 = (const float*)d_in[3];
    const float* eb2 = (const float*)d_in[4];
    const float* dw1 = (const float*)d_in[5];
    const float* db1 = (const float*)d_in[6];
    const float* dw2 = (const float*)d_in[7];
    const float* db2 = (const float*)d_in[8];
    float* out = (float*)d_out;

    __half *px, *ph, *pz, *w1, *w2, *w3, *w4;
    cudaGetSymbolAddress((void**)&px, g_x);
    cudaGetSymbolAddress((void**)&ph, g_h);
    cudaGetSymbolAddress((void**)&pz, g_z);
    cudaGetSymbolAddress((void**)&w1, g_wt1);
    cudaGetSymbolAddress((void**)&w2, g_wt2);
    cudaGetSymbolAddress((void**)&w3, g_wt3);
    cudaGetSymbolAddress((void**)&w4, g_wt4);

    // prep: x -> fp16; transpose weights -> [N,K] fp16
    f32_to_f16_kernel<<<2048, 256>>>((const float4*)x, (__half2*)px, (BATCH * IN_CH) / 4);
    dim3 tb(32, 8);
    transpose_f16_kernel<<<dim3(IN_CH / 32, IN_CH / 32), tb>>>(ew1, w1, IN_CH, IN_CH);
    transpose_f16_kernel<<<dim3(COMP  / 32, IN_CH / 32), tb>>>(ew2, w2, IN_CH, COMP);
    transpose_f16_kernel<<<dim3(IN_CH / 32, COMP  / 32), tb>>>(dw1, w3, COMP, IN_CH);
    transpose_f16_kernel<<<dim3(IN_CH / 32, IN_CH / 32), tb>>>(dw2, w4, IN_CH, IN_CH);

    cudaFuncSetAttribute((void*)gemm_mma<EP_RELU, __half>,        cudaFuncAttributeMaxDynamicSharedMemorySize, SMEM_BYTES);
    cudaFuncSetAttribute((void*)gemm_mma<EP_CLAMP_NOISE, __half>, cudaFuncAttributeMaxDynamicSharedMemorySize, SMEM_BYTES);
    cudaFuncSetAttribute((void*)gemm_mma<EP_PLAIN, float>,        cudaFuncAttributeMaxDynamicSharedMemorySize, SMEM_BYTES);

    // G1: h = relu(x @ enc_w1 + b)            [16384, 4096], K=4096
    gemm_mma<EP_RELU, __half><<<dim3(IN_CH / BN, BATCH / BM), 256, SMEM_BYTES>>>(px, w1, eb1, ph, BATCH, IN_CH, IN_CH);
    // G2: z = clamp(h @ enc_w2 + b) + awgn    [16384, 512],  K=4096
    gemm_mma<EP_CLAMP_NOISE, __half><<<dim3(COMP / BN, BATCH / BM), 256, SMEM_BYTES>>>(ph, w2, eb2, pz, BATCH, COMP, IN_CH);
    // G3: h = relu(z @ dec_w1 + b)            [16384, 4096], K=512
    gemm_mma<EP_RELU, __half><<<dim3(IN_CH / BN, BATCH / BM), 256, SMEM_BYTES>>>(pz, w3, db1, ph, BATCH, IN_CH, COMP);
    // G4: out = h @ dec_w2 + b                [16384, 4096], K=4096
    gemm_mma<EP_PLAIN, float><<<dim3(IN_CH / BN, BATCH / BM), 256, SMEM_BYTES>>>(ph, w4, db2, out, BATCH, IN_CH, IN_CH);
}

// round 14
// speedup vs baseline: 1.0596x; 1.0006x over previous
#include <cuda_runtime.h>
#include <cuda_fp16.h>
#include <math.h>
#include <stdint.h>

#define BATCH 16384
#define IN_CH 4096
#define COMP  512

// ---------------- scratch (__device__ globals; no allocation allowed) ----------------
__device__ __half g_x [(size_t)BATCH * IN_CH];   // fp16 x
__device__ __half g_h [(size_t)BATCH * IN_CH];   // fp16 activations (reused)
__device__ __half g_z [(size_t)BATCH * COMP];
__device__ __half g_w1[(size_t)IN_CH * IN_CH];   // enc_w1 [K,N] fp16 (native layout)
__device__ __half g_w2[(size_t)IN_CH * COMP];
__device__ __half g_w3[(size_t)COMP  * IN_CH];
__device__ __half g_w4[(size_t)IN_CH * IN_CH];

// ---------------- helpers ----------------
__device__ __forceinline__ uint32_t smem_u32(const void* p) {
    uint32_t a;
    asm("{ .reg .u64 t; cvta.to.shared.u64 t, %1; cvt.u32.u64 %0, t; }" : "=r"(a) : "l"(p));
    return a;
}

#define CP_ASYNC16(saddr, gaddr) \
    asm volatile("cp.async.cg.shared.global [%0], [%1], 16;" :: "r"(saddr), "l"(gaddr) : "memory")
#define CP_COMMIT() asm volatile("cp.async.commit_group;" ::: "memory")
#define CP_WAIT(n)  asm volatile("cp.async.wait_group %0;" :: "n"(n) : "memory")

__device__ __forceinline__ void ldsm4(uint32_t* r, uint32_t addr) {
    asm volatile("ldmatrix.sync.aligned.m8n8.x4.shared.b16 {%0,%1,%2,%3}, [%4];"
                 : "=r"(r[0]), "=r"(r[1]), "=r"(r[2]), "=r"(r[3]) : "r"(addr));
}
__device__ __forceinline__ void ldsm4t(uint32_t* r, uint32_t addr) {
    asm volatile("ldmatrix.sync.aligned.m8n8.x4.trans.shared.b16 {%0,%1,%2,%3}, [%4];"
                 : "=r"(r[0]), "=r"(r[1]), "=r"(r[2]), "=r"(r[3]) : "r"(addr));
}

__device__ __forceinline__ void mma_f16(float* d, uint32_t a0, uint32_t a1, uint32_t a2, uint32_t a3,
                                        uint32_t b0, uint32_t b1) {
    asm volatile("mma.sync.aligned.m16n8k16.row.col.f32.f16.f16.f32 "
                 "{%0,%1,%2,%3}, {%4,%5,%6,%7}, {%8,%9}, {%0,%1,%2,%3};"
                 : "+f"(d[0]), "+f"(d[1]), "+f"(d[2]), "+f"(d[3])
                 : "r"(a0), "r"(a1), "r"(a2), "r"(a3), "r"(b0), "r"(b1));
}

// ---------------- JAX Threefry noise (verified bit-exact in round 0) ----------------
__device__ __forceinline__ unsigned rotl32(unsigned v, int r) { return (v << r) | (v >> (32 - r)); }
__device__ __forceinline__ unsigned threefry2x32_xor(unsigned c_hi, unsigned c_lo) {
    const unsigned k1 = 0u, k2 = 42u, k3 = 0x1BD11BDAu ^ k1 ^ k2;
    unsigned x0 = c_hi + k1, x1 = c_lo + k2;
#define TFR(r) { x0 += x1; x1 = rotl32(x1, (r)); x1 ^= x0; }
    TFR(13) TFR(15) TFR(26) TFR(6)
    x0 += k2; x1 += k3 + 1u;
    TFR(17) TFR(29) TFR(16) TFR(24)
    x0 += k3; x1 += k1 + 2u;
    TFR(13) TFR(15) TFR(26) TFR(6)
    x0 += k1; x1 += k2 + 3u;
    TFR(17) TFR(29) TFR(16) TFR(24)
    x0 += k2; x1 += k3 + 4u;
    TFR(13) TFR(15) TFR(26) TFR(6)
    x0 += k3; x1 += k1 + 5u;
#undef TFR
    return x0 ^ x1;
}
__device__ __forceinline__ float jax_awgn_noise(unsigned idx) {
    unsigned bits = threefry2x32_xor(0u, idx);
    float f = __uint_as_float((bits >> 9) | 0x3F800000u) - 1.0f;
    const float lo = -0.99999994f;
    float u = fmaxf(lo, fmaf(f, 2.0f, lo));
    return 1.41421356f * erfinvf(u) * 0.223341852f;
}

// ---------------- prep kernel (pure streaming convert) ----------------
__global__ void f32_to_f16_kernel(const float4* __restrict__ in, __half2* __restrict__ out, int n4) {
    for (int i = blockIdx.x * blockDim.x + threadIdx.x; i < n4; i += gridDim.x * blockDim.x) {
        float4 v = in[i];
        out[i * 2]     = __floats2half2_rn(v.x, v.y);
        out[i * 2 + 1] = __floats2half2_rn(v.z, v.w);
    }
}

// ---------------- fp16 mma.sync GEMM (A ldmatrix, B trans-ldmatrix from [K,N]) ----------------
// C[M,N] = ep(A[M,K] @ W + bias), A fp16 [M,K], W fp16 [K,N] native. CTA tile 128x128x64.
// 8 warps as 4(M) x 2(N): warp tile 32x64 = 2 x 8 m16n8k16 tiles per k16-step (4 steps/chunk).

#define BM 128
#define BN 128
#define BK 64
#define NSTAGE 3
#define LDTA 72                           // A row stride (halves): conflict-free LDSM+STS
#define LDTB 136                          // B row stride (halves): conflict-free trans-LDSM+STS
#define TILE_A_H (128 * LDTA)             // 9216 halves
#define TILE_B_H (64 * LDTB)              // 8704 halves
#define STAGE_H (TILE_A_H + TILE_B_H)     // 17920 halves
#define SMEM_BYTES (NSTAGE * STAGE_H * 2) // 107520

enum { EP_RELU = 0, EP_CLAMP_NOISE = 1, EP_PLAIN = 2 };

// A tile: 128 rows x 64 halves. STS banks (36r+4q) mod 32 conflict-free; 128B/row coalesced.
__device__ __forceinline__ void load_tileA(__half* sdst, const __half* gsrc, int ldg, int tid) {
#pragma unroll
    for (int i = 0; i < 4; i++) {
        int idx = tid + i * 256;           // 0..1023
        int row = idx >> 3;
        int q   = idx & 7;
        CP_ASYNC16(smem_u32(sdst + row * LDTA + q * 8), gsrc + (size_t)row * ldg + q * 8);
    }
}
// B tile: 64 k-rows x 128 n-halves from [K,N]. 16 lanes/row -> 256B coalesced reads;
// STS banks (68r+4q) mod 32: each 8-lane phase covers distinct banks (conflict-free).
__device__ __forceinline__ void load_tileB(__half* sdst, const __half* gsrc, int ldg, int tid) {
#pragma unroll
    for (int i = 0; i < 4; i++) {
        int idx = tid + i * 256;           // 0..1023
        int row = idx >> 4;                // 0..63 (k)
        int q   = idx & 15;                // 16B chunk (8 n-values)
        CP_ASYNC16(smem_u32(sdst + row * LDTB + q * 8), gsrc + (size_t)row * ldg + q * 8);
    }
}

template <int MODE, typename OutT>
__global__ __launch_bounds__(256, 2)
void gemm_mma(const __half* __restrict__ A, const __half* __restrict__ B,
              const float* __restrict__ bias, OutT* __restrict__ C,
              int M, int N, int K)
{
    extern __shared__ __half sm[];
    const int tid = threadIdx.x;
    const int wid = tid >> 5;
    const int lane = tid & 31;
    const int g = lane >> 2;              // fragment row
    const int tig = lane & 3;
    const int qt = lane >> 3;             // ldmatrix tile id 0..3
    const int rr = lane & 7;              // row within ldmatrix tile

    const int n0 = blockIdx.x * BN;
    const int m0 = blockIdx.y * BM;
    const int warp_m = (wid >> 1) * 32;   // 0,32,64,96
    const int warp_n = (wid & 1) * 64;    // 0,64
    const int nchunk = K >> 6;            // BK=64

    const __half* Ab = A + (size_t)m0 * K;
    const __half* Bb = B + n0;            // [K,N]: column offset

    const uint32_t smb = smem_u32(sm);
    // A ldmatrix per-lane byte offsets (k=0), per-ks advance = 32 bytes
    uint32_t a_loff[2];
#pragma unroll
    for (int mt = 0; mt < 2; mt++)
        a_loff[mt] = ((warp_m + mt * 16 + ((qt & 1) << 3) + rr) * LDTA + ((qt >> 1) << 3)) * 2;
    // B trans-ldmatrix per-lane byte offsets (k=0), per-ks advance = 16*LDTB*2 bytes.
    // Lane groups: 0-7 (k0-7, n..n+7), 8-15 (k8-15, n..n+7), 16-23 (k0-7, n+8..), 24-31 (k8-15, n+8..)
    uint32_t b_loff[4];
#pragma unroll
    for (int p = 0; p < 4; p++)
        b_loff[p] = (TILE_A_H + (((qt & 1) << 3) + rr) * LDTB + warp_n + p * 16 + ((qt >> 1) << 3)) * 2;

    float acc[2][8][4];
#pragma unroll
    for (int mt = 0; mt < 2; mt++)
#pragma unroll
        for (int nt = 0; nt < 8; nt++)
#pragma unroll
            for (int q = 0; q < 4; q++) acc[mt][nt][q] = 0.0f;

    // prologue
#pragma unroll
    for (int s = 0; s < NSTAGE - 1; s++) {
        __half* st = sm + s * STAGE_H;
        load_tileA(st, Ab + s * BK, K, tid);
        load_tileB(st + TILE_A_H, Bb + (size_t)(s * BK) * N, N, tid);
        CP_COMMIT();
    }

    for (int c = 0; c < nchunk; c++) {
        CP_WAIT(NSTAGE - 2);
        __syncthreads();

        if (c + NSTAGE - 1 < nchunk) {
            int s = (c + NSTAGE - 1) % NSTAGE;
            __half* st = sm + s * STAGE_H;
            load_tileA(st, Ab + (c + NSTAGE - 1) * BK, K, tid);
            load_tileB(st + TILE_A_H, Bb + (size_t)((c + NSTAGE - 1) * BK) * N, N, tid);
            CP_COMMIT();
        }

        const uint32_t stg = smb + (uint32_t)((c % NSTAGE) * STAGE_H * 2);

#pragma unroll
        for (int ks = 0; ks < 4; ks++) {              // four k16 steps per chunk
            const uint32_t kba = ks * 32;             // A: 16 halves = 32 bytes
            const uint32_t kbb = ks * (16 * LDTB * 2); // B: 16 k-rows
            uint32_t af[2][4], bf[4][4];
            ldsm4(af[0], stg + a_loff[0] + kba);
            ldsm4(af[1], stg + a_loff[1] + kba);
#pragma unroll
            for (int p = 0; p < 4; p++) ldsm4t(bf[p], stg + b_loff[p] + kbb);
#pragma unroll
            for (int mt = 0; mt < 2; mt++)
#pragma unroll
                for (int nt = 0; nt < 8; nt++)
                    mma_f16(acc[mt][nt], af[mt][0], af[mt][1], af[mt][2], af[mt][3],
                            bf[nt >> 1][(nt & 1) * 2], bf[nt >> 1][(nt & 1) * 2 + 1]);
        }
    }
    CP_WAIT(0);

    // ---- epilogue ----
#pragma unroll
    for (int mt = 0; mt < 2; mt++) {
        const int row_a = m0 + warp_m + mt * 16 + g;
        const int row_b = row_a + 8;
#pragma unroll
        for (int nt = 0; nt < 8; nt++) {
            const int col = n0 + warp_n + nt * 8 + tig * 2;
            const float b0 = bias[col], b1 = bias[col + 1];
            float v0 = acc[mt][nt][0] + b0;
            float v1 = acc[mt][nt][1] + b1;
            float v2 = acc[mt][nt][2] + b0;
            float v3 = acc[mt][nt][3] + b1;
            if (MODE == EP_RELU) {
                v0 = fmaxf(v0, 0.0f); v1 = fmaxf(v1, 0.0f);
                v2 = fmaxf(v2, 0.0f); v3 = fmaxf(v3, 0.0f);
            } else if (MODE == EP_CLAMP_NOISE) {
                v0 = fminf(fmaxf(v0, 0.0f), 1.0f) + jax_awgn_noise((unsigned)((size_t)row_a * N + col));
                v1 = fminf(fmaxf(v1, 0.0f), 1.0f) + jax_awgn_noise((unsigned)((size_t)row_a * N + col + 1));
                v2 = fminf(fmaxf(v2, 0.0f), 1.0f) + jax_awgn_noise((unsigned)((size_t)row_b * N + col));
                v3 = fminf(fmaxf(v3, 0.0f), 1.0f) + jax_awgn_noise((unsigned)((size_t)row_b * N + col + 1));
            }
            if (sizeof(OutT) == 2) {
                __half* Ch = (__half*)C;
                *(__half2*)(Ch + (size_t)row_a * N + col) = __floats2half2_rn(v0, v1);
                *(__half2*)(Ch + (size_t)row_b * N + col) = __floats2half2_rn(v2, v3);
            } else {
                float* Cf = (float*)C;
                *(float2*)(Cf + (size_t)row_a * N + col) = make_float2(v0, v1);
                *(float2*)(Cf + (size_t)row_b * N + col) = make_float2(v2, v3);
            }
        }
    }
}

// ---------------- host launch ----------------
extern "C" void kernel_launch(void* const* d_in, const int* in_sizes, int n_in,
                              void* d_out, int out_size)
{
    (void)in_sizes; (void)n_in; (void)out_size;
    const float* x   = (const float*)d_in[0];
    const float* ew1 = (const float*)d_in[1];
    const float* eb1 = (const float*)d_in[2];
    const float* ew2 = (const float*)d_in[3];
    const float* eb2 = (const float*)d_in[4];
    const float* dw1 = (const float*)d_in[5];
    const float* db1 = (const float*)d_in[6];
    const float* dw2 = (const float*)d_in[7];
    const float* db2 = (const float*)d_in[8];
    float* out = (float*)d_out;

    __half *px, *ph, *pz, *w1, *w2, *w3, *w4;
    cudaGetSymbolAddress((void**)&px, g_x);
    cudaGetSymbolAddress((void**)&ph, g_h);
    cudaGetSymbolAddress((void**)&pz, g_z);
    cudaGetSymbolAddress((void**)&w1, g_w1);
    cudaGetSymbolAddress((void**)&w2, g_w2);
    cudaGetSymbolAddress((void**)&w3, g_w3);
    cudaGetSymbolAddress((void**)&w4, g_w4);

    // prep: pure streaming f32 -> f16 converts (no transposes needed with trans-ldmatrix)
    f32_to_f16_kernel<<<2048, 256>>>((const float4*)x,   (__half2*)px, (BATCH * IN_CH) / 4);
    f32_to_f16_kernel<<<2048, 256>>>((const float4*)ew1, (__half2*)w1, (IN_CH * IN_CH) / 4);
    f32_to_f16_kernel<<<512,  256>>>((const float4*)ew2, (__half2*)w2, (IN_CH * COMP) / 4);
    f32_to_f16_kernel<<<512,  256>>>((const float4*)dw1, (__half2*)w3, (COMP * IN_CH) / 4);
    f32_to_f16_kernel<<<2048, 256>>>((const float4*)dw2, (__half2*)w4, (IN_CH * IN_CH) / 4);

    cudaFuncSetAttribute((void*)gemm_mma<EP_RELU, __half>,        cudaFuncAttributeMaxDynamicSharedMemorySize, SMEM_BYTES);
    cudaFuncSetAttribute((void*)gemm_mma<EP_CLAMP_NOISE, __half>, cudaFuncAttributeMaxDynamicSharedMemorySize, SMEM_BYTES);
    cudaFuncSetAttribute((void*)gemm_mma<EP_PLAIN, float>,        cudaFuncAttributeMaxDynamicSharedMemorySize, SMEM_BYTES);

    // G1: h = relu(x @ enc_w1 + b)            [16384, 4096], K=4096
    gemm_mma<EP_RELU, __half><<<dim3(IN_CH / BN, BATCH / BM), 256, SMEM_BYTES>>>(px, w1, eb1, ph, BATCH, IN_CH, IN_CH);
    // G2: z = clamp(h @ enc_w2 + b) + awgn    [16384, 512],  K=4096
    gemm_mma<EP_CLAMP_NOISE, __half><<<dim3(COMP / BN, BATCH / BM), 256, SMEM_BYTES>>>(ph, w2, eb2, pz, BATCH, COMP, IN_CH);
    // G3: h = relu(z @ dec_w1 + b)            [16384, 4096], K=512
    gemm_mma<EP_RELU, __half><<<dim3(IN_CH / BN, BATCH / BM), 256, SMEM_BYTES>>>(pz, w3, db1, ph, BATCH, IN_CH, COMP);
    // G4: out = h @ dec_w2 + b                [16384, 4096], K=4096
    gemm_mma<EP_PLAIN, float><<<dim3(IN_CH / BN, BATCH / BM), 256, SMEM_BYTES>>>(ph, w4, db2, out, BATCH, IN_CH, IN_CH);
}

// round 15
// speedup vs baseline: 1.0914x; 1.0299x over previous
#include <cuda_runtime.h>
#include <cuda_fp16.h>
#include <math.h>
#include <stdint.h>

#define BATCH 16384
#define IN_CH 4096
#define COMP  512

// ---------------- scratch (__device__ globals; no allocation allowed) ----------------
__device__ __half g_x [(size_t)BATCH * IN_CH];   // fp16 x
__device__ __half g_h [(size_t)BATCH * IN_CH];   // fp16 activations (reused)
__device__ __half g_z [(size_t)BATCH * COMP];
__device__ __half g_wt1[(size_t)IN_CH * IN_CH];  // enc_w1^T  [N,K] fp16
__device__ __half g_wt2[(size_t)COMP  * IN_CH];
__device__ __half g_wt3[(size_t)IN_CH * COMP];
__device__ __half g_wt4[(size_t)IN_CH * IN_CH];

// ---------------- helpers ----------------
__device__ __forceinline__ uint32_t smem_u32(const void* p) {
    uint32_t a;
    asm("{ .reg .u64 t; cvta.to.shared.u64 t, %1; cvt.u32.u64 %0, t; }" : "=r"(a) : "l"(p));
    return a;
}

#define CP_ASYNC16(saddr, gaddr) \
    asm volatile("cp.async.cg.shared.global [%0], [%1], 16;" :: "r"(saddr), "l"(gaddr) : "memory")
#define CP_COMMIT() asm volatile("cp.async.commit_group;" ::: "memory")
#define CP_WAIT(n)  asm volatile("cp.async.wait_group %0;" :: "n"(n) : "memory")

__device__ __forceinline__ void ldsm4(uint32_t* r, uint32_t addr) {
    asm volatile("ldmatrix.sync.aligned.m8n8.x4.shared.b16 {%0,%1,%2,%3}, [%4];"
                 : "=r"(r[0]), "=r"(r[1]), "=r"(r[2]), "=r"(r[3]) : "r"(addr));
}

__device__ __forceinline__ void mma_f16(float* d, uint32_t a0, uint32_t a1, uint32_t a2, uint32_t a3,
                                        uint32_t b0, uint32_t b1) {
    asm volatile("mma.sync.aligned.m16n8k16.row.col.f32.f16.f16.f32 "
                 "{%0,%1,%2,%3}, {%4,%5,%6,%7}, {%8,%9}, {%0,%1,%2,%3};"
                 : "+f"(d[0]), "+f"(d[1]), "+f"(d[2]), "+f"(d[3])
                 : "r"(a0), "r"(a1), "r"(a2), "r"(a3), "r"(b0), "r"(b1));
}

// ---------------- JAX Threefry noise (verified bit-exact in round 0) ----------------
__device__ __forceinline__ unsigned rotl32(unsigned v, int r) { return (v << r) | (v >> (32 - r)); }
__device__ __forceinline__ unsigned threefry2x32_xor(unsigned c_hi, unsigned c_lo) {
    const unsigned k1 = 0u, k2 = 42u, k3 = 0x1BD11BDAu ^ k1 ^ k2;
    unsigned x0 = c_hi + k1, x1 = c_lo + k2;
#define TFR(r) { x0 += x1; x1 = rotl32(x1, (r)); x1 ^= x0; }
    TFR(13) TFR(15) TFR(26) TFR(6)
    x0 += k2; x1 += k3 + 1u;
    TFR(17) TFR(29) TFR(16) TFR(24)
    x0 += k3; x1 += k1 + 2u;
    TFR(13) TFR(15) TFR(26) TFR(6)
    x0 += k1; x1 += k2 + 3u;
    TFR(17) TFR(29) TFR(16) TFR(24)
    x0 += k2; x1 += k3 + 4u;
    TFR(13) TFR(15) TFR(26) TFR(6)
    x0 += k3; x1 += k1 + 5u;
#undef TFR
    return x0 ^ x1;
}
__device__ __forceinline__ float jax_awgn_noise(unsigned idx) {
    unsigned bits = threefry2x32_xor(0u, idx);
    float f = __uint_as_float((bits >> 9) | 0x3F800000u) - 1.0f;
    const float lo = -0.99999994f;
    float u = fmaxf(lo, fmaf(f, 2.0f, lo));
    return 1.41421356f * erfinvf(u) * 0.223341852f;
}

// ---------------- prep kernels ----------------
__global__ void f32_to_f16_kernel(const float4* __restrict__ in, __half2* __restrict__ out, int n4) {
    for (int i = blockIdx.x * blockDim.x + threadIdx.x; i < n4; i += gridDim.x * blockDim.x) {
        float4 v = in[i];
        out[i * 2]     = __floats2half2_rn(v.x, v.y);
        out[i * 2 + 1] = __floats2half2_rn(v.z, v.w);
    }
}
// out[c][r] = f16(in[r][c]); in is [R, C] f32
__global__ void transpose_f16_kernel(const float* __restrict__ in, __half* __restrict__ out, int R, int C) {
    __shared__ float t[32][33];
    int c0 = blockIdx.x * 32, r0 = blockIdx.y * 32;
    int x = threadIdx.x, y = threadIdx.y;
    for (int i = y; i < 32; i += 8) t[i][x] = in[(size_t)(r0 + i) * C + c0 + x];
    __syncthreads();
    for (int i = y; i < 32; i += 8) out[(size_t)(c0 + i) * R + r0 + x] = __float2half_rn(t[x][i]);
}

// ---------------- fp16 mma.sync GEMM (ldmatrix b16, BK=64) — exact R11 ----------------
// C[M,N] = ep(A[M,K] @ B^T + bias), A,B fp16, B stored [N,K]. CTA tile 128x128x64.
// 8 warps as 4(M) x 2(N): warp tile 32x64 = 2 x 8 m16n8k16 tiles per k16-step (4 steps/chunk).

#define BM 128
#define BN 128
#define BK 64
#define NSTAGE 3
#define LDT 72                            // halves; 144B row stride -> conflict-free LDSM+STS
#define TILE_H (128 * LDT)                // 9216 halves per operand tile
#define STAGE_H (2 * TILE_H)              // 18432 halves
#define SMEM_BYTES (NSTAGE * STAGE_H * 2) // 110592

enum { EP_RELU = 0, EP_CLAMP_NOISE = 1, EP_PLAIN = 2 };

// load a 128x64 fp16 tile (row stride ldg halves) into padded smem tile (256 threads).
// STS banks (36r+4q) mod 32 — conflict-free; 8 lanes read 128B contiguous (coalesced).
__device__ __forceinline__ void load_tile16(__half* sdst, const __half* gsrc, int ldg, int tid) {
#pragma unroll
    for (int i = 0; i < 4; i++) {
        int idx = tid + i * 256;           // 0..1023
        int row = idx >> 3;
        int q   = idx & 7;                 // 16B (8 halves) chunk within 64-half row
        uint32_t sa = smem_u32(sdst + row * LDT + q * 8);
        const __half* ga = gsrc + (size_t)row * ldg + q * 8;
        CP_ASYNC16(sa, ga);
    }
}

template <int MODE, typename OutT>
__global__ __launch_bounds__(256, 2)
void gemm_mma(const __half* __restrict__ A, const __half* __restrict__ B,
              const float* __restrict__ bias, OutT* __restrict__ C,
              int M, int N, int K)
{
    extern __shared__ __half sm[];
    const int tid = threadIdx.x;
    const int wid = tid >> 5;
    const int lane = tid & 31;
    const int g = lane >> 2;              // fragment row
    const int tig = lane & 3;
    const int qt = lane >> 3;             // ldmatrix tile id 0..3
    const int rr = lane & 7;              // row within ldmatrix tile

    const int n0 = blockIdx.x * BN;
    const int m0 = blockIdx.y * BM;
    const int warp_m = (wid >> 1) * 32;   // 0,32,64,96
    const int warp_n = (wid & 1) * 64;    // 0,64
    const int nchunk = K >> 6;            // BK=64

    const __half* Ab = A + (size_t)m0 * K;
    const __half* Bb = B + (size_t)n0 * K;

    const uint32_t smb = smem_u32(sm);
    // per-lane ldmatrix byte offsets (k=0) within a stage
    uint32_t a_loff[2], b_loff[4];
#pragma unroll
    for (int mt = 0; mt < 2; mt++)
        a_loff[mt] = ((warp_m + mt * 16 + ((qt & 1) << 3) + rr) * LDT + ((qt >> 1) << 3)) * 2;
#pragma unroll
    for (int p = 0; p < 4; p++)
        b_loff[p] = (TILE_H + (warp_n + p * 16 + ((qt >> 1) << 3) + rr) * LDT + ((qt & 1) << 3)) * 2;

    float acc[2][8][4];
#pragma unroll
    for (int mt = 0; mt < 2; mt++)
#pragma unroll
        for (int nt = 0; nt < 8; nt++)
#pragma unroll
            for (int q = 0; q < 4; q++) acc[mt][nt][q] = 0.0f;

    // prologue: issue stages 0..NSTAGE-2
#pragma unroll
    for (int s = 0; s < NSTAGE - 1; s++) {
        __half* st = sm + s * STAGE_H;
        load_tile16(st, Ab + s * BK, K, tid);
        load_tile16(st + TILE_H, Bb + s * BK, K, tid);
        CP_COMMIT();
    }

    for (int c = 0; c < nchunk; c++) {
        CP_WAIT(NSTAGE - 2);
        __syncthreads();

        if (c + NSTAGE - 1 < nchunk) {
            int s = (c + NSTAGE - 1) % NSTAGE;
            __half* st = sm + s * STAGE_H;
            load_tile16(st, Ab + (c + NSTAGE - 1) * BK, K, tid);
            load_tile16(st + TILE_H, Bb + (c + NSTAGE - 1) * BK, K, tid);
            CP_COMMIT();
        }

        const uint32_t stg = smb + (uint32_t)((c % NSTAGE) * STAGE_H * 2);

#pragma unroll
        for (int ks = 0; ks < 4; ks++) {              // four k16 steps per chunk
            const uint32_t kb = ks * 32;              // 16 halves = 32 bytes
            uint32_t af[2][4], bf[4][4];
            ldsm4(af[0], stg + a_loff[0] + kb);
            ldsm4(af[1], stg + a_loff[1] + kb);
#pragma unroll
            for (int p = 0; p < 4; p++) ldsm4(bf[p], stg + b_loff[p] + kb);
#pragma unroll
            for (int mt = 0; mt < 2; mt++)
#pragma unroll
                for (int nt = 0; nt < 8; nt++)
                    mma_f16(acc[mt][nt], af[mt][0], af[mt][1], af[mt][2], af[mt][3],
                            bf[nt >> 1][(nt & 1) * 2], bf[nt >> 1][(nt & 1) * 2 + 1]);
        }
    }
    CP_WAIT(0);

    // ---- epilogue ----
#pragma unroll
    for (int mt = 0; mt < 2; mt++) {
        const int row_a = m0 + warp_m + mt * 16 + g;
        const int row_b = row_a + 8;
#pragma unroll
        for (int nt = 0; nt < 8; nt++) {
            const int col = n0 + warp_n + nt * 8 + tig * 2;
            const float b0 = bias[col], b1 = bias[col + 1];
            float v0 = acc[mt][nt][0] + b0;
            float v1 = acc[mt][nt][1] + b1;
            float v2 = acc[mt][nt][2] + b0;
            float v3 = acc[mt][nt][3] + b1;
            if (MODE == EP_RELU) {
                v0 = fmaxf(v0, 0.0f); v1 = fmaxf(v1, 0.0f);
                v2 = fmaxf(v2, 0.0f); v3 = fmaxf(v3, 0.0f);
            } else if (MODE == EP_CLAMP_NOISE) {
                v0 = fminf(fmaxf(v0, 0.0f), 1.0f) + jax_awgn_noise((unsigned)((size_t)row_a * N + col));
                v1 = fminf(fmaxf(v1, 0.0f), 1.0f) + jax_awgn_noise((unsigned)((size_t)row_a * N + col + 1));
                v2 = fminf(fmaxf(v2, 0.0f), 1.0f) + jax_awgn_noise((unsigned)((size_t)row_b * N + col));
                v3 = fminf(fmaxf(v3, 0.0f), 1.0f) + jax_awgn_noise((unsigned)((size_t)row_b * N + col + 1));
            }
            if (sizeof(OutT) == 2) {
                __half* Ch = (__half*)C;
                *(__half2*)(Ch + (size_t)row_a * N + col) = __floats2half2_rn(v0, v1);
                *(__half2*)(Ch + (size_t)row_b * N + col) = __floats2half2_rn(v2, v3);
            } else {
                float* Cf = (float*)C;
                *(float2*)(Cf + (size_t)row_a * N + col) = make_float2(v0, v1);
                *(float2*)(Cf + (size_t)row_b * N + col) = make_float2(v2, v3);
            }
        }
    }
}

// ---------------- host launch ----------------
extern "C" void kernel_launch(void* const* d_in, const int* in_sizes, int n_in,
                              void* d_out, int out_size)
{
    (void)in_sizes; (void)n_in; (void)out_size;
    const float* x   = (const float*)d_in[0];
    const float* ew1 = (const float*)d_in[1];
    const float* eb1 = (const float*)d_in[2];
    const float* ew2 = (const float*)d_in[3];
    const float* eb2 = (const float*)d_in[4];
    const float* dw1 = (const float*)d_in[5];
    const float* db1 = (const float*)d_in[6];
    const float* dw2 = (const float*)d_in[7];
    const float* db2 = (const float*)d_in[8];
    float* out = (float*)d_out;

    __half *px, *ph, *pz, *w1, *w2, *w3, *w4;
    cudaGetSymbolAddress((void**)&px, g_x);
    cudaGetSymbolAddress((void**)&ph, g_h);
    cudaGetSymbolAddress((void**)&pz, g_z);
    cudaGetSymbolAddress((void**)&w1, g_wt1);
    cudaGetSymbolAddress((void**)&w2, g_wt2);
    cudaGetSymbolAddress((void**)&w3, g_wt3);
    cudaGetSymbolAddress((void**)&w4, g_wt4);

    // one-time side stream + events for prep overlap (host resources only)
    static cudaStream_t s1 = nullptr;
    static cudaEvent_t eFork = nullptr, eJoin = nullptr;
    if (!s1) {
        cudaStreamCreateWithFlags(&s1, cudaStreamNonBlocking);
        cudaEventCreateWithFlags(&eFork, cudaEventDisableTiming);
        cudaEventCreateWithFlags(&eJoin, cudaEventDisableTiming);
    }

    dim3 tb(32, 8);
    // fork: side stream does the 4 weight transposes while main stream converts x
    cudaEventRecord(eFork, 0);
    cudaStreamWaitEvent(s1, eFork, 0);
    transpose_f16_kernel<<<dim3(IN_CH / 32, IN_CH / 32), tb, 0, s1>>>(ew1, w1, IN_CH, IN_CH);
    transpose_f16_kernel<<<dim3(COMP  / 32, IN_CH / 32), tb, 0, s1>>>(ew2, w2, IN_CH, COMP);
    transpose_f16_kernel<<<dim3(IN_CH / 32, COMP  / 32), tb, 0, s1>>>(dw1, w3, COMP, IN_CH);
    transpose_f16_kernel<<<dim3(IN_CH / 32, IN_CH / 32), tb, 0, s1>>>(dw2, w4, IN_CH, IN_CH);
    cudaEventRecord(eJoin, s1);

    f32_to_f16_kernel<<<2048, 256>>>((const float4*)x, (__half2*)px, (BATCH * IN_CH) / 4);
    cudaStreamWaitEvent(0, eJoin, 0);   // join before GEMMs

    cudaFuncSetAttribute((void*)gemm_mma<EP_RELU, __half>,        cudaFuncAttributeMaxDynamicSharedMemorySize, SMEM_BYTES);
    cudaFuncSetAttribute((void*)gemm_mma<EP_CLAMP_NOISE, __half>, cudaFuncAttributeMaxDynamicSharedMemorySize, SMEM_BYTES);
    cudaFuncSetAttribute((void*)gemm_mma<EP_PLAIN, float>,        cudaFuncAttributeMaxDynamicSharedMemorySize, SMEM_BYTES);

    // G1: h = relu(x @ enc_w1 + b)            [16384, 4096], K=4096
    gemm_mma<EP_RELU, __half><<<dim3(IN_CH / BN, BATCH / BM), 256, SMEM_BYTES>>>(px, w1, eb1, ph, BATCH, IN_CH, IN_CH);
    // G2: z = clamp(h @ enc_w2 + b) + awgn    [16384, 512],  K=4096
    gemm_mma<EP_CLAMP_NOISE, __half><<<dim3(COMP / BN, BATCH / BM), 256, SMEM_BYTES>>>(ph, w2, eb2, pz, BATCH, COMP, IN_CH);
    // G3: h = relu(z @ dec_w1 + b)            [16384, 4096], K=512
    gemm_mma<EP_RELU, __half><<<dim3(IN_CH / BN, BATCH / BM), 256, SMEM_BYTES>>>(pz, w3, db1, ph, BATCH, IN_CH, COMP);
    // G4: out = h @ dec_w2 + b                [16384, 4096], K=4096
    gemm_mma<EP_PLAIN, float><<<dim3(IN_CH / BN, BATCH / BM), 256, SMEM_BYTES>>>(ph, w4, db2, out, BATCH, IN_CH, IN_CH);
}

// round 16
// speedup vs baseline: 1.0987x; 1.0067x over previous
#include <cuda_runtime.h>
#include <cuda_fp16.h>
#include <math.h>
#include <stdint.h>

#define BATCH 16384
#define IN_CH 4096
#define COMP  512

// ---------------- scratch (__device__ globals; no allocation allowed) ----------------
__device__ __half g_x [(size_t)BATCH * IN_CH];   // fp16 x
__device__ __half g_h [(size_t)BATCH * IN_CH];   // fp16 activations (reused)
__device__ __half g_z [(size_t)BATCH * COMP];
__device__ __half g_wt1[(size_t)IN_CH * IN_CH];  // enc_w1^T  [N,K] fp16
__device__ __half g_wt2[(size_t)COMP  * IN_CH];
__device__ __half g_wt3[(size_t)IN_CH * COMP];
__device__ __half g_wt4[(size_t)IN_CH * IN_CH];

// ---------------- helpers ----------------
__device__ __forceinline__ uint32_t smem_u32(const void* p) {
    uint32_t a;
    asm("{ .reg .u64 t; cvta.to.shared.u64 t, %1; cvt.u32.u64 %0, t; }" : "=r"(a) : "l"(p));
    return a;
}

#define CP_ASYNC16(saddr, gaddr) \
    asm volatile("cp.async.cg.shared.global [%0], [%1], 16;" :: "r"(saddr), "l"(gaddr) : "memory")
#define CP_COMMIT() asm volatile("cp.async.commit_group;" ::: "memory")
#define CP_WAIT(n)  asm volatile("cp.async.wait_group %0;" :: "n"(n) : "memory")

__device__ __forceinline__ void ldsm4(uint32_t* r, uint32_t addr) {
    asm volatile("ldmatrix.sync.aligned.m8n8.x4.shared.b16 {%0,%1,%2,%3}, [%4];"
                 : "=r"(r[0]), "=r"(r[1]), "=r"(r[2]), "=r"(r[3]) : "r"(addr));
}

__device__ __forceinline__ void mma_f16(float* d, uint32_t a0, uint32_t a1, uint32_t a2, uint32_t a3,
                                        uint32_t b0, uint32_t b1) {
    asm volatile("mma.sync.aligned.m16n8k16.row.col.f32.f16.f16.f32 "
                 "{%0,%1,%2,%3}, {%4,%5,%6,%7}, {%8,%9}, {%0,%1,%2,%3};"
                 : "+f"(d[0]), "+f"(d[1]), "+f"(d[2]), "+f"(d[3])
                 : "r"(a0), "r"(a1), "r"(a2), "r"(a3), "r"(b0), "r"(b1));
}

// ---------------- JAX Threefry noise (verified bit-exact in round 0) ----------------
__device__ __forceinline__ unsigned rotl32(unsigned v, int r) { return (v << r) | (v >> (32 - r)); }
__device__ __forceinline__ unsigned threefry2x32_xor(unsigned c_hi, unsigned c_lo) {
    const unsigned k1 = 0u, k2 = 42u, k3 = 0x1BD11BDAu ^ k1 ^ k2;
    unsigned x0 = c_hi + k1, x1 = c_lo + k2;
#define TFR(r) { x0 += x1; x1 = rotl32(x1, (r)); x1 ^= x0; }
    TFR(13) TFR(15) TFR(26) TFR(6)
    x0 += k2; x1 += k3 + 1u;
    TFR(17) TFR(29) TFR(16) TFR(24)
    x0 += k3; x1 += k1 + 2u;
    TFR(13) TFR(15) TFR(26) TFR(6)
    x0 += k1; x1 += k2 + 3u;
    TFR(17) TFR(29) TFR(16) TFR(24)
    x0 += k2; x1 += k3 + 4u;
    TFR(13) TFR(15) TFR(26) TFR(6)
    x0 += k3; x1 += k1 + 5u;
#undef TFR
    return x0 ^ x1;
}
__device__ __forceinline__ float jax_awgn_noise(unsigned idx) {
    unsigned bits = threefry2x32_xor(0u, idx);
    float f = __uint_as_float((bits >> 9) | 0x3F800000u) - 1.0f;
    const float lo = -0.99999994f;
    float u = fmaxf(lo, fmaf(f, 2.0f, lo));
    return 1.41421356f * erfinvf(u) * 0.223341852f;
}

// ---------------- prep kernels ----------------
__global__ void f32_to_f16_kernel(const float4* __restrict__ in, __half2* __restrict__ out, int n4) {
    for (int i = blockIdx.x * blockDim.x + threadIdx.x; i < n4; i += gridDim.x * blockDim.x) {
        float4 v = in[i];
        out[i * 2]     = __floats2half2_rn(v.x, v.y);
        out[i * 2 + 1] = __floats2half2_rn(v.z, v.w);
    }
}
// out[c][r] = f16(in[r][c]); in is [R, C] f32
__global__ void transpose_f16_kernel(const float* __restrict__ in, __half* __restrict__ out, int R, int C) {
    __shared__ float t[32][33];
    int c0 = blockIdx.x * 32, r0 = blockIdx.y * 32;
    int x = threadIdx.x, y = threadIdx.y;
    for (int i = y; i < 32; i += 8) t[i][x] = in[(size_t)(r0 + i) * C + c0 + x];
    __syncthreads();
    for (int i = y; i < 32; i += 8) out[(size_t)(c0 + i) * R + r0 + x] = __float2half_rn(t[x][i]);
}

// ---------------- fp16 mma.sync GEMM (ldmatrix b16, BK=64) — exact R11 ----------------
// C[M,N] = ep(A[M,K] @ B^T + bias), A,B fp16, B stored [N,K]. CTA tile 128x128x64.
// 8 warps as 4(M) x 2(N): warp tile 32x64 = 2 x 8 m16n8k16 tiles per k16-step (4 steps/chunk).

#define BM 128
#define BN 128
#define BK 64
#define NSTAGE 3
#define LDT 72                            // halves; 144B row stride -> conflict-free LDSM+STS
#define TILE_H (128 * LDT)                // 9216 halves per operand tile
#define STAGE_H (2 * TILE_H)              // 18432 halves
#define SMEM_BYTES (NSTAGE * STAGE_H * 2) // 110592

enum { EP_RELU = 0, EP_CLAMP_NOISE = 1, EP_PLAIN = 2 };

// load a 128x64 fp16 tile (row stride ldg halves) into padded smem tile (256 threads).
// STS banks (36r+4q) mod 32 — conflict-free; 8 lanes read 128B contiguous (coalesced).
__device__ __forceinline__ void load_tile16(__half* sdst, const __half* gsrc, int ldg, int tid) {
#pragma unroll
    for (int i = 0; i < 4; i++) {
        int idx = tid + i * 256;           // 0..1023
        int row = idx >> 3;
        int q   = idx & 7;                 // 16B (8 halves) chunk within 64-half row
        uint32_t sa = smem_u32(sdst + row * LDT + q * 8);
        const __half* ga = gsrc + (size_t)row * ldg + q * 8;
        CP_ASYNC16(sa, ga);
    }
}

template <int MODE, typename OutT>
__global__ __launch_bounds__(256, 2)
void gemm_mma(const __half* __restrict__ A, const __half* __restrict__ B,
              const float* __restrict__ bias, OutT* __restrict__ C,
              int M, int N, int K)
{
    extern __shared__ __half sm[];
    const int tid = threadIdx.x;
    const int wid = tid >> 5;
    const int lane = tid & 31;
    const int g = lane >> 2;              // fragment row
    const int tig = lane & 3;
    const int qt = lane >> 3;             // ldmatrix tile id 0..3
    const int rr = lane & 7;              // row within ldmatrix tile

    const int n0 = blockIdx.x * BN;
    const int m0 = blockIdx.y * BM;
    const int warp_m = (wid >> 1) * 32;   // 0,32,64,96
    const int warp_n = (wid & 1) * 64;    // 0,64
    const int nchunk = K >> 6;            // BK=64

    const __half* Ab = A + (size_t)m0 * K;
    const __half* Bb = B + (size_t)n0 * K;

    const uint32_t smb = smem_u32(sm);
    // per-lane ldmatrix byte offsets (k=0) within a stage
    uint32_t a_loff[2], b_loff[4];
#pragma unroll
    for (int mt = 0; mt < 2; mt++)
        a_loff[mt] = ((warp_m + mt * 16 + ((qt & 1) << 3) + rr) * LDT + ((qt >> 1) << 3)) * 2;
#pragma unroll
    for (int p = 0; p < 4; p++)
        b_loff[p] = (TILE_H + (warp_n + p * 16 + ((qt >> 1) << 3) + rr) * LDT + ((qt & 1) << 3)) * 2;

    float acc[2][8][4];
#pragma unroll
    for (int mt = 0; mt < 2; mt++)
#pragma unroll
        for (int nt = 0; nt < 8; nt++)
#pragma unroll
            for (int q = 0; q < 4; q++) acc[mt][nt][q] = 0.0f;

    // prologue: issue stages 0..NSTAGE-2
#pragma unroll
    for (int s = 0; s < NSTAGE - 1; s++) {
        __half* st = sm + s * STAGE_H;
        load_tile16(st, Ab + s * BK, K, tid);
        load_tile16(st + TILE_H, Bb + s * BK, K, tid);
        CP_COMMIT();
    }

    for (int c = 0; c < nchunk; c++) {
        CP_WAIT(NSTAGE - 2);
        __syncthreads();

        if (c + NSTAGE - 1 < nchunk) {
            int s = (c + NSTAGE - 1) % NSTAGE;
            __half* st = sm + s * STAGE_H;
            load_tile16(st, Ab + (c + NSTAGE - 1) * BK, K, tid);
            load_tile16(st + TILE_H, Bb + (c + NSTAGE - 1) * BK, K, tid);
            CP_COMMIT();
        }

        const uint32_t stg = smb + (uint32_t)((c % NSTAGE) * STAGE_H * 2);

#pragma unroll
        for (int ks = 0; ks < 4; ks++) {              // four k16 steps per chunk
            const uint32_t kb = ks * 32;              // 16 halves = 32 bytes
            uint32_t af[2][4], bf[4][4];
            ldsm4(af[0], stg + a_loff[0] + kb);
            ldsm4(af[1], stg + a_loff[1] + kb);
#pragma unroll
            for (int p = 0; p < 4; p++) ldsm4(bf[p], stg + b_loff[p] + kb);
#pragma unroll
            for (int mt = 0; mt < 2; mt++)
#pragma unroll
                for (int nt = 0; nt < 8; nt++)
                    mma_f16(acc[mt][nt], af[mt][0], af[mt][1], af[mt][2], af[mt][3],
                            bf[nt >> 1][(nt & 1) * 2], bf[nt >> 1][(nt & 1) * 2 + 1]);
        }
    }
    CP_WAIT(0);

    // ---- epilogue ----
#pragma unroll
    for (int mt = 0; mt < 2; mt++) {
        const int row_a = m0 + warp_m + mt * 16 + g;
        const int row_b = row_a + 8;
#pragma unroll
        for (int nt = 0; nt < 8; nt++) {
            const int col = n0 + warp_n + nt * 8 + tig * 2;
            const float b0 = bias[col], b1 = bias[col + 1];
            float v0 = acc[mt][nt][0] + b0;
            float v1 = acc[mt][nt][1] + b1;
            float v2 = acc[mt][nt][2] + b0;
            float v3 = acc[mt][nt][3] + b1;
            if (MODE == EP_RELU) {
                v0 = fmaxf(v0, 0.0f); v1 = fmaxf(v1, 0.0f);
                v2 = fmaxf(v2, 0.0f); v3 = fmaxf(v3, 0.0f);
            } else if (MODE == EP_CLAMP_NOISE) {
                v0 = fminf(fmaxf(v0, 0.0f), 1.0f) + jax_awgn_noise((unsigned)((size_t)row_a * N + col));
                v1 = fminf(fmaxf(v1, 0.0f), 1.0f) + jax_awgn_noise((unsigned)((size_t)row_a * N + col + 1));
                v2 = fminf(fmaxf(v2, 0.0f), 1.0f) + jax_awgn_noise((unsigned)((size_t)row_b * N + col));
                v3 = fminf(fmaxf(v3, 0.0f), 1.0f) + jax_awgn_noise((unsigned)((size_t)row_b * N + col + 1));
            }
            if (sizeof(OutT) == 2) {
                __half* Ch = (__half*)C;
                *(__half2*)(Ch + (size_t)row_a * N + col) = __floats2half2_rn(v0, v1);
                *(__half2*)(Ch + (size_t)row_b * N + col) = __floats2half2_rn(v2, v3);
            } else {
                float* Cf = (float*)C;
                *(float2*)(Cf + (size_t)row_a * N + col) = make_float2(v0, v1);
                *(float2*)(Cf + (size_t)row_b * N + col) = make_float2(v2, v3);
            }
        }
    }
}

// ---------------- host launch ----------------
extern "C" void kernel_launch(void* const* d_in, const int* in_sizes, int n_in,
                              void* d_out, int out_size)
{
    (void)in_sizes; (void)n_in; (void)out_size;
    const float* x   = (const float*)d_in[0];
    const float* ew1 = (const float*)d_in[1];
    const float* eb1 = (const float*)d_in[2];
    const float* ew2 = (const float*)d_in[3];
    const float* eb2 = (const float*)d_in[4];
    const float* dw1 = (const float*)d_in[5];
    const float* db1 = (const float*)d_in[6];
    const float* dw2 = (const float*)d_in[7];
    const float* db2 = (const float*)d_in[8];
    float* out = (float*)d_out;

    __half *px, *ph, *pz, *w1, *w2, *w3, *w4;
    cudaGetSymbolAddress((void**)&px, g_x);
    cudaGetSymbolAddress((void**)&ph, g_h);
    cudaGetSymbolAddress((void**)&pz, g_z);
    cudaGetSymbolAddress((void**)&w1, g_wt1);
    cudaGetSymbolAddress((void**)&w2, g_wt2);
    cudaGetSymbolAddress((void**)&w3, g_wt3);
    cudaGetSymbolAddress((void**)&w4, g_wt4);

    // one-time side stream + events (host resources only)
    static cudaStream_t s1 = nullptr;
    static cudaEvent_t eFork = nullptr, eW1 = nullptr, eW234 = nullptr;
    if (!s1) {
        cudaStreamCreateWithFlags(&s1, cudaStreamNonBlocking);
        cudaEventCreateWithFlags(&eFork, cudaEventDisableTiming);
        cudaEventCreateWithFlags(&eW1,   cudaEventDisableTiming);
        cudaEventCreateWithFlags(&eW234, cudaEventDisableTiming);
    }

    cudaFuncSetAttribute((void*)gemm_mma<EP_RELU, __half>,        cudaFuncAttributeMaxDynamicSharedMemorySize, SMEM_BYTES);
    cudaFuncSetAttribute((void*)gemm_mma<EP_CLAMP_NOISE, __half>, cudaFuncAttributeMaxDynamicSharedMemorySize, SMEM_BYTES);
    cudaFuncSetAttribute((void*)gemm_mma<EP_PLAIN, float>,        cudaFuncAttributeMaxDynamicSharedMemorySize, SMEM_BYTES);

    dim3 tb(32, 8);
    // fork side stream
    cudaEventRecord(eFork, 0);
    cudaStreamWaitEvent(s1, eFork, 0);
    // side: w1 first (G1 dependency), then the rest (hidden under G1)
    transpose_f16_kernel<<<dim3(IN_CH / 32, IN_CH / 32), tb, 0, s1>>>(ew1, w1, IN_CH, IN_CH);
    cudaEventRecord(eW1, s1);
    transpose_f16_kernel<<<dim3(COMP  / 32, IN_CH / 32), tb, 0, s1>>>(ew2, w2, IN_CH, COMP);
    transpose_f16_kernel<<<dim3(IN_CH / 32, COMP  / 32), tb, 0, s1>>>(dw1, w3, COMP, IN_CH);
    transpose_f16_kernel<<<dim3(IN_CH / 32, IN_CH / 32), tb, 0, s1>>>(dw2, w4, IN_CH, IN_CH);
    cudaEventRecord(eW234, s1);

    // main: convert x concurrently with w1 transpose
    f32_to_f16_kernel<<<2048, 256>>>((const float4*)x, (__half2*)px, (BATCH * IN_CH) / 4);
    cudaStreamWaitEvent(0, eW1, 0);     // G1 needs px + w1 only

    // G1: h = relu(x @ enc_w1 + b)            [16384, 4096], K=4096
    gemm_mma<EP_RELU, __half><<<dim3(IN_CH / BN, BATCH / BM), 256, SMEM_BYTES>>>(px, w1, eb1, ph, BATCH, IN_CH, IN_CH);

    cudaStreamWaitEvent(0, eW234, 0);   // w2/w3/w4 transposed under G1
    // G2: z = clamp(h @ enc_w2 + b) + awgn    [16384, 512],  K=4096
    gemm_mma<EP_CLAMP_NOISE, __half><<<dim3(COMP / BN, BATCH / BM), 256, SMEM_BYTES>>>(ph, w2, eb2, pz, BATCH, COMP, IN_CH);
    // G3: h = relu(z @ dec_w1 + b)            [16384, 4096], K=512
    gemm_mma<EP_RELU, __half><<<dim3(IN_CH / BN, BATCH / BM), 256, SMEM_BYTES>>>(pz, w3, db1, ph, BATCH, IN_CH, COMP);
    // G4: out = h @ dec_w2 + b                [16384, 4096], K=4096
    gemm_mma<EP_PLAIN, float><<<dim3(IN_CH / BN, BATCH / BM), 256, SMEM_BYTES>>>(ph, w4, db2, out, BATCH, IN_CH, IN_CH);
}